// round 1
// baseline (speedup 1.0000x reference)
#include <cuda_runtime.h>
#include <math.h>

// Problem constants
#define Bsz 8
#define Nseq 2048
#define Cdim 768
#define Hn 12
#define Dh 64
#define Mlm 32
#define BH (Bsz*Hn)            // 96
#define QK_SCALE 0.35355339059327373f  // 64^-0.25

// ---------------- scratch (device globals; no runtime alloc allowed) -------
__device__ float g_qkv[(size_t)3 * BH * Nseq * Dh];   // [3][96][2048][64] ~151MB
__device__ float g_lm[(size_t)2 * BH * Mlm * Dh];     // Q_l then K_l
__device__ float g_inv[(size_t)BH * Mlm * Mlm];       // pinv(kernel_2)
__device__ float g_F[(size_t)BH * Mlm * Dh];          // kernel_3 @ V
__device__ float g_X[(size_t)Bsz * Nseq * Cdim];      // pre-proj activations ~50MB

// ============================================================================
// SGEMM 128x128x8, 256 threads, 8x8 per thread. Epilogue variants via template
// ============================================================================
template<int EPI>
__global__ __launch_bounds__(256)
void sgemm128(const float* __restrict__ A, const float* __restrict__ B,
              const float* __restrict__ bias, float* __restrict__ C,
              int Kdim, int Ndim)
{
    __shared__ float As[8][128];
    __shared__ float Bs[8][128];
    const int tid = threadIdx.x;
    const int bx = blockIdx.x, by = blockIdx.y;

    const int a_row = tid >> 1;
    const int a_col = (tid & 1) << 2;
    const int b_row = tid >> 5;
    const int b_col = (tid & 31) << 2;

    const float* Ap = A + (size_t)(by * 128 + a_row) * Kdim + a_col;
    const float* Bp = B + (size_t)b_row * Ndim + bx * 128 + b_col;

    const int tr = (tid >> 4) << 3;
    const int tc = (tid & 15) << 3;

    float acc[8][8];
#pragma unroll
    for (int i = 0; i < 8; i++)
#pragma unroll
        for (int j = 0; j < 8; j++) acc[i][j] = 0.f;

    for (int k0 = 0; k0 < Kdim; k0 += 8) {
        float4 av = *(const float4*)(Ap + k0);
        float4 bv = *(const float4*)(Bp + (size_t)k0 * Ndim);
        As[a_col + 0][a_row] = av.x;
        As[a_col + 1][a_row] = av.y;
        As[a_col + 2][a_row] = av.z;
        As[a_col + 3][a_row] = av.w;
        *(float4*)&Bs[b_row][b_col] = bv;
        __syncthreads();
#pragma unroll
        for (int k = 0; k < 8; k++) {
            float ar[8], br[8];
            *(float4*)&ar[0] = *(const float4*)&As[k][tr];
            *(float4*)&ar[4] = *(const float4*)&As[k][tr + 4];
            *(float4*)&br[0] = *(const float4*)&Bs[k][tc];
            *(float4*)&br[4] = *(const float4*)&Bs[k][tc + 4];
#pragma unroll
            for (int i = 0; i < 8; i++)
#pragma unroll
                for (int j = 0; j < 8; j++)
                    acc[i][j] += ar[i] * br[j];
        }
        __syncthreads();
    }

    if (EPI == 0) {
        // qkv epilogue: scatter into g_qkv[[which][b*12+h][n][dd]], scale Q,K
#pragma unroll
        for (int i = 0; i < 8; i++) {
            int r = by * 128 + tr + i;
            int b = r >> 11;          // / 2048
            int n = r & 2047;
            // 8 consecutive cols never cross a 64-wide head-dim block (tc%8==0)
            int c0 = bx * 128 + tc;
            int which = c0 / 768;
            int rem = c0 - which * 768;
            int h = rem >> 6;
            int dd0 = rem & 63;
            float sc = (which < 2) ? QK_SCALE : 1.0f;
            float* dst = g_qkv + (((size_t)which * BH + b * Hn + h) * Nseq + n) * Dh + dd0;
#pragma unroll
            for (int j = 0; j < 8; j++)
                dst[j] = acc[i][j] * sc;
        }
    } else {
        // proj epilogue: C[r][c] = acc + bias[c]
#pragma unroll
        for (int i = 0; i < 8; i++) {
            int r = by * 128 + tr + i;
            float* Crow = C + (size_t)r * Ndim + bx * 128 + tc;
#pragma unroll
            for (int j = 0; j < 8; j++)
                Crow[j] = acc[i][j] + bias[bx * 128 + tc + j];
        }
    }
}

// ============================================================================
// Landmark pooling: mean over contiguous chunks of 64
// ============================================================================
__global__ void pool_kernel()
{
    int idx = blockIdx.x * 256 + threadIdx.x;
    const int total = 2 * BH * Mlm * Dh; // 393216
    if (idx >= total) return;
    int dd = idx & 63;
    int i = (idx >> 6) & 31;
    int rest = idx >> 11;            // which*96 + bh
    const float* src = g_qkv + (size_t)rest * Nseq * Dh + (size_t)(i * 64) * Dh + dd;
    float s = 0.f;
#pragma unroll 8
    for (int t = 0; t < 64; t++) s += src[(size_t)t * Dh];
    g_lm[idx] = s * (1.0f / 64.0f);
}

// ============================================================================
// kernel_2 = softmax(Q_l K_l^T) + Newton-Schulz pseudo-inverse (6 iters)
// one block of 32x32 threads per (b,h)
// ============================================================================
__global__ __launch_bounds__(1024)
void newton_kernel()
{
    int bh = blockIdx.x;
    int j = threadIdx.x, i = threadIdx.y;
    __shared__ float Ql[32][65], Kl[32][65];
    __shared__ float Km[32][33], Vm[32][33], KV[32][33], Tm[32][33];
    __shared__ float red[1];

    int t = i * 32 + j;
    for (int e = t; e < Mlm * Dh; e += 1024) {
        Ql[e >> 6][e & 63] = g_lm[(size_t)bh * (Mlm * Dh) + e];
        Kl[e >> 6][e & 63] = g_lm[(size_t)(BH + bh) * (Mlm * Dh) + e];
    }
    __syncthreads();

    float s = 0.f;
#pragma unroll
    for (int dd = 0; dd < 64; dd++) s += Ql[i][dd] * Kl[j][dd];
    // row softmax (warp == row, lane == j)
    float mx = s;
    for (int o = 16; o; o >>= 1) mx = fmaxf(mx, __shfl_xor_sync(~0u, mx, o));
    float p = expf(s - mx);
    float sm = p;
    for (int o = 16; o; o >>= 1) sm += __shfl_xor_sync(~0u, sm, o);
    p /= sm;
    Km[i][j] = p;
    __syncthreads();

    // denom = max over columns of column sums
    if (i == 0) {
        float cs = 0.f;
        for (int r = 0; r < 32; r++) cs += Km[r][j];
        float m2 = cs;
        for (int o = 16; o; o >>= 1) m2 = fmaxf(m2, __shfl_xor_sync(~0u, m2, o));
        if (j == 0) red[0] = m2;
    }
    __syncthreads();
    float denom = red[0];
    Vm[i][j] = Km[j][i] / denom;
    __syncthreads();

    for (int it = 0; it < 6; it++) {
        float kv = 0.f;
#pragma unroll
        for (int k = 0; k < 32; k++) kv += Km[i][k] * Vm[k][j];
        KV[i][j] = kv;
        __syncthreads();
        Tm[i][j] = (i == j ? 7.0f : 0.0f) - kv;
        __syncthreads();
        float u = 0.f;
#pragma unroll
        for (int k = 0; k < 32; k++) u += KV[i][k] * Tm[k][j];
        __syncthreads();
        Tm[i][j] = (i == j ? 15.0f : 0.0f) - u;
        __syncthreads();
        u = 0.f;
#pragma unroll
        for (int k = 0; k < 32; k++) u += KV[i][k] * Tm[k][j];
        __syncthreads();
        Tm[i][j] = (i == j ? 13.0f : 0.0f) - u;
        __syncthreads();
        u = 0.f;
#pragma unroll
        for (int k = 0; k < 32; k++) u += Vm[i][k] * Tm[k][j];
        u *= 0.25f;
        __syncthreads();
        Vm[i][j] = u;
        __syncthreads();
    }
    g_inv[((size_t)bh * 32 + i) * 32 + j] = Vm[i][j];
}

// ============================================================================
// F = softmax(Q_l K^T, axis=N) @ V  — streaming (flash-style) per (b,h)
// 512 threads = 16 warps, 2 landmark rows per warp
// ============================================================================
__global__ __launch_bounds__(512)
void flash_k3()
{
    int bh = blockIdx.x;
    int tid = threadIdx.x;
    int w = tid >> 5, l = tid & 31;
    __shared__ float Ql[32][65];
    __shared__ float Ks[32][65], Vs[32][65];
    __shared__ float Ps[32][33];

    const float* Kg = g_qkv + ((size_t)1 * BH + bh) * Nseq * Dh;
    const float* Vg = g_qkv + ((size_t)2 * BH + bh) * Nseq * Dh;

    for (int e = tid; e < Mlm * Dh; e += 512)
        Ql[e >> 6][e & 63] = g_lm[(size_t)bh * (Mlm * Dh) + e];

    const int r0 = w * 2, r1 = r0 + 1;
    float m0 = -1e30f, l0 = 0.f, o00 = 0.f, o01 = 0.f;
    float m1 = -1e30f, l1 = 0.f, o10 = 0.f, o11 = 0.f;

    for (int t0 = 0; t0 < Nseq; t0 += 32) {
        __syncthreads();
        for (int e = tid; e < 32 * Dh; e += 512) {
            int r = e >> 6, c = e & 63;
            Ks[r][c] = Kg[(size_t)(t0 + r) * Dh + c];
            Vs[r][c] = Vg[(size_t)(t0 + r) * Dh + c];
        }
        __syncthreads();

        // ---- row r0 ----
        {
            float s = 0.f;
#pragma unroll
            for (int dd = 0; dd < 64; dd++) s += Ql[r0][dd] * Ks[l][dd];
            float tm = s;
            for (int o = 16; o; o >>= 1) tm = fmaxf(tm, __shfl_xor_sync(~0u, tm, o));
            float nm = fmaxf(m0, tm);
            float alpha = expf(m0 - nm);
            float p = expf(s - nm);
            float ps = p;
            for (int o = 16; o; o >>= 1) ps += __shfl_xor_sync(~0u, ps, o);
            l0 = l0 * alpha + ps;
            o00 *= alpha; o01 *= alpha;
            Ps[r0][l] = p;
            __syncwarp();
#pragma unroll
            for (int k = 0; k < 32; k++) {
                float pk = Ps[r0][k];
                o00 += pk * Vs[k][2 * l];
                o01 += pk * Vs[k][2 * l + 1];
            }
            m0 = nm;
        }
        // ---- row r1 ----
        {
            float s = 0.f;
#pragma unroll
            for (int dd = 0; dd < 64; dd++) s += Ql[r1][dd] * Ks[l][dd];
            float tm = s;
            for (int o = 16; o; o >>= 1) tm = fmaxf(tm, __shfl_xor_sync(~0u, tm, o));
            float nm = fmaxf(m1, tm);
            float alpha = expf(m1 - nm);
            float p = expf(s - nm);
            float ps = p;
            for (int o = 16; o; o >>= 1) ps += __shfl_xor_sync(~0u, ps, o);
            l1 = l1 * alpha + ps;
            o10 *= alpha; o11 *= alpha;
            Ps[r1][l] = p;
            __syncwarp();
#pragma unroll
            for (int k = 0; k < 32; k++) {
                float pk = Ps[r1][k];
                o10 += pk * Vs[k][2 * l];
                o11 += pk * Vs[k][2 * l + 1];
            }
            m1 = nm;
        }
    }
    float i0 = 1.f / l0, i1 = 1.f / l1;
    float* F0 = g_F + ((size_t)bh * Mlm + r0) * Dh;
    float* F1 = g_F + ((size_t)bh * Mlm + r1) * Dh;
    F0[2 * l] = o00 * i0; F0[2 * l + 1] = o01 * i0;
    F1[2 * l] = o10 * i1; F1[2 * l + 1] = o11 * i1;
}

// ============================================================================
// X = softmax(Q K_l^T) @ (inv2 @ F)  — per (b,h, chunk of 128 rows)
// writes directly in [B, N, C] layout
// ============================================================================
__global__ __launch_bounds__(128)
void nys_out()
{
    int bh = blockIdx.y;
    int b = bh / Hn, h = bh - b * Hn;
    int chunk = blockIdx.x;
    int tid = threadIdx.x;

    __shared__ float Kl[32][65];
    __shared__ float Fs[32][65];
    __shared__ float Gs[32][65];
    __shared__ float invs[32][33];

    for (int e = tid; e < Mlm * Dh; e += 128) {
        Kl[e >> 6][e & 63] = g_lm[(size_t)(BH + bh) * (Mlm * Dh) + e];
        Fs[e >> 6][e & 63] = g_F[(size_t)bh * (Mlm * Dh) + e];
    }
    for (int e = tid; e < Mlm * Mlm; e += 128)
        invs[e >> 5][e & 31] = g_inv[(size_t)bh * (Mlm * Mlm) + e];
    __syncthreads();

    // G = inv2 @ F  (32x64)
    for (int e = tid; e < Mlm * Dh; e += 128) {
        int r = e >> 6, c = e & 63;
        float s = 0.f;
#pragma unroll
        for (int k = 0; k < 32; k++) s += invs[r][k] * Fs[k][c];
        Gs[r][c] = s;
    }
    __syncthreads();

    int n = chunk * 128 + tid;
    const float* Qg = g_qkv + ((size_t)bh * Nseq + n) * Dh;
    float q[64];
#pragma unroll
    for (int e = 0; e < 16; e++)
        *(float4*)&q[4 * e] = *(const float4*)&Qg[4 * e];

    float logits[32];
#pragma unroll
    for (int j = 0; j < 32; j++) {
        float s = 0.f;
#pragma unroll
        for (int dd = 0; dd < 64; dd++) s += q[dd] * Kl[j][dd];
        logits[j] = s;
    }
    float mx = -1e30f;
#pragma unroll
    for (int j = 0; j < 32; j++) mx = fmaxf(mx, logits[j]);
    float sum = 0.f;
#pragma unroll
    for (int j = 0; j < 32; j++) { logits[j] = expf(logits[j] - mx); sum += logits[j]; }
    float is = 1.f / sum;
#pragma unroll
    for (int j = 0; j < 32; j++) logits[j] *= is;

    float* Xp = g_X + ((size_t)b * Nseq + n) * Cdim + h * Dh;
#pragma unroll
    for (int d4 = 0; d4 < 16; d4++) {
        float4 o = make_float4(0.f, 0.f, 0.f, 0.f);
#pragma unroll
        for (int j = 0; j < 32; j++) {
            float pj = logits[j];
            o.x += pj * Gs[j][4 * d4 + 0];
            o.y += pj * Gs[j][4 * d4 + 1];
            o.z += pj * Gs[j][4 * d4 + 2];
            o.w += pj * Gs[j][4 * d4 + 3];
        }
        *(float4*)&Xp[4 * d4] = o;
    }
}

// ============================================================================
extern "C" void kernel_launch(void* const* d_in, const int* in_sizes, int n_in,
                              void* d_out, int out_size)
{
    const float* x      = (const float*)d_in[0];  // [8,2048,768]
    const float* w_qkv  = (const float*)d_in[1];  // [768,2304]
    const float* w_proj = (const float*)d_in[2];  // [768,768]
    const float* b_proj = (const float*)d_in[3];  // [768]
    float* out = (float*)d_out;                   // [8,2048,768]

    float* gX;
    cudaGetSymbolAddress((void**)&gX, g_X);

    // 1. qkv GEMM (M=16384, N=2304, K=768) with scatter+scale epilogue
    sgemm128<0><<<dim3(2304 / 128, 16384 / 128), 256>>>(x, w_qkv, nullptr, nullptr, Cdim, 3 * Cdim);
    // 2. landmark pooling
    pool_kernel<<<(2 * BH * Mlm * Dh + 255) / 256, 256>>>();
    // 3. kernel_2 + Newton-Schulz inverse
    newton_kernel<<<BH, dim3(32, 32)>>>();
    // 4. F = softmax(Q_l K^T) @ V
    flash_k3<<<BH, 512>>>();
    // 5. X = softmax(Q K_l^T) @ (inv @ F) -> [B,N,C]
    nys_out<<<dim3(Nseq / 128, BH), 128>>>();
    // 6. proj GEMM + bias (M=16384, N=768, K=768)
    sgemm128<1><<<dim3(768 / 128, 16384 / 128), 256>>>(gX, w_proj, b_proj, out, Cdim, Cdim);
}

// round 4
// speedup vs baseline: 1.6720x; 1.6720x over previous
#include <cuda_runtime.h>
#include <cuda_bf16.h>
#include <math.h>
#include <stdint.h>

// Problem constants
#define Bsz 8
#define Nseq 2048
#define Cdim 768
#define Hn 12
#define Dh 64
#define Mlm 32
#define BH (Bsz*Hn)            // 96
#define KC 2304                // concatenated K for split GEMM (3*768)
#define QK_SCALE 0.35355339059327373f  // 64^-0.25

// ---------------- scratch (device globals; no runtime alloc allowed) -------
__device__ float g_qkv[(size_t)3 * BH * Nseq * Dh];         // [3][96][2048][64]
__device__ float g_lm[(size_t)2 * BH * Mlm * Dh];           // Q_l then K_l
__device__ float g_inv[(size_t)BH * Mlm * Mlm];             // pinv(kernel_2)
__device__ float g_F[(size_t)BH * Mlm * Dh];                // kernel_3 @ V
__device__ float g_Fpart[(size_t)BH * 8 * Mlm * 66];        // partial flash outputs
__device__ __nv_bfloat16 g_Acat[(size_t)16384 * KC];        // [Ah|Ah|Al] of x
__device__ __nv_bfloat16 g_Xcat[(size_t)16384 * KC];        // [Xh|Xh|Xl] of attention out
__device__ __nv_bfloat16 g_Bq[(size_t)KC * KC];             // w_qkv^T split-cat [N=2304][K'=2304]
__device__ __nv_bfloat16 g_Bp[(size_t)Cdim * KC];           // w_proj^T split-cat [N=768][K'=2304]

// ============================================================================
// PTX helpers (baseline ISA only: cp.async / ldmatrix / mma.sync)
// ============================================================================
__device__ __forceinline__ uint32_t smem_u32(const void* p) {
    uint32_t a;
    asm("{ .reg .u64 t; cvta.to.shared.u64 t, %1; cvt.u32.u64 %0, t; }" : "=r"(a) : "l"(p));
    return a;
}
#define CP16(dst, src) \
    asm volatile("cp.async.cg.shared.global [%0], [%1], 16;" :: "r"(dst), "l"(src))
#define CP_COMMIT() asm volatile("cp.async.commit_group;" ::: "memory")
#define CP_WAIT1()  asm volatile("cp.async.wait_group 1;" ::: "memory")
#define CP_WAIT0()  asm volatile("cp.async.wait_group 0;" ::: "memory")

__device__ __forceinline__ void ldsm_x4(uint32_t& r0, uint32_t& r1, uint32_t& r2, uint32_t& r3, uint32_t addr) {
    asm volatile("ldmatrix.sync.aligned.m8n8.x4.shared.b16 {%0,%1,%2,%3}, [%4];"
                 : "=r"(r0), "=r"(r1), "=r"(r2), "=r"(r3) : "r"(addr));
}
__device__ __forceinline__ void ldsm_x2(uint32_t& r0, uint32_t& r1, uint32_t addr) {
    asm volatile("ldmatrix.sync.aligned.m8n8.x2.shared.b16 {%0,%1}, [%2];"
                 : "=r"(r0), "=r"(r1) : "r"(addr));
}
__device__ __forceinline__ void mma16816(float* d, const uint32_t* a, const uint32_t* b) {
    asm volatile("mma.sync.aligned.m16n8k16.row.col.f32.bf16.bf16.f32 "
                 "{%0,%1,%2,%3}, {%4,%5,%6,%7}, {%8,%9}, {%0,%1,%2,%3};"
                 : "+f"(d[0]), "+f"(d[1]), "+f"(d[2]), "+f"(d[3])
                 : "r"(a[0]), "r"(a[1]), "r"(a[2]), "r"(a[3]), "r"(b[0]), "r"(b[1]));
}

// ============================================================================
// conv_a: x [16384][768] f32 -> g_Acat [16384][2304] bf16  ([Ah|Ah|Al])
// ============================================================================
__global__ __launch_bounds__(256) void conv_a(const float* __restrict__ X)
{
    int idx = blockIdx.x * 256 + threadIdx.x;   // 16384*192 total
    int r = idx / 192, c = (idx - r * 192) * 4;
    float4 v = *(const float4*)(X + (size_t)r * Cdim + c);
    float f[4] = {v.x, v.y, v.z, v.w};
    __nv_bfloat16 hi[4], lo[4];
#pragma unroll
    for (int i = 0; i < 4; i++) {
        hi[i] = __float2bfloat16(f[i]);
        lo[i] = __float2bfloat16(f[i] - __bfloat162float(hi[i]));
    }
    __nv_bfloat16* row = g_Acat + (size_t)r * KC;
    __nv_bfloat162 h0 = {hi[0], hi[1]}, h1 = {hi[2], hi[3]};
    __nv_bfloat162 l0 = {lo[0], lo[1]}, l1 = {lo[2], lo[3]};
    *(__nv_bfloat162*)(row + c) = h0;        *(__nv_bfloat162*)(row + c + 2) = h1;
    *(__nv_bfloat162*)(row + 768 + c) = h0;  *(__nv_bfloat162*)(row + 768 + c + 2) = h1;
    *(__nv_bfloat162*)(row + 1536 + c) = l0; *(__nv_bfloat162*)(row + 1536 + c + 2) = l1;
}

// ============================================================================
// conv_w: W [768][Nw] f32 -> Bt [Nw][2304] bf16 transposed split-cat [Bh|Bl|Bh]
// ============================================================================
__global__ __launch_bounds__(256) void conv_w(const float* __restrict__ W,
                                              __nv_bfloat16* __restrict__ Bt, int Nw)
{
    __shared__ float tile[32][33];
    int n0 = blockIdx.x * 32, k0 = blockIdx.y * 32;
    for (int i = threadIdx.y; i < 32; i += 8)
        tile[i][threadIdx.x] = W[(size_t)(k0 + i) * Nw + n0 + threadIdx.x];
    __syncthreads();
    for (int i = threadIdx.y; i < 32; i += 8) {
        int n = n0 + i, k = k0 + threadIdx.x;
        float v = tile[threadIdx.x][i];
        __nv_bfloat16 hi = __float2bfloat16(v);
        __nv_bfloat16 lo = __float2bfloat16(v - __bfloat162float(hi));
        __nv_bfloat16* row = Bt + (size_t)n * KC;
        row[k] = hi;
        row[768 + k] = lo;
        row[1536 + k] = hi;
    }
}

// ============================================================================
// HMMA bf16 GEMM: D[128x128] = A_cat[128xKC] * B_cat[128xKC]^T
// 256 threads = 8 warps (2x4), warp tile 64x32, BK=32, cp.async double buffer
// EPI 0: scatter into g_qkv with QK scale.  EPI 1: +bias -> out.
// ============================================================================
#define SROW 40   // smem row stride in bf16 (80B: 16B-aligned, ldmatrix conflict-free)

template<int EPI>
__global__ __launch_bounds__(256)
void hmma_gemm(const float* __restrict__ bias, float* __restrict__ out)
{
    __shared__ __align__(16) __nv_bfloat16 sA[2][128 * SROW];
    __shared__ __align__(16) __nv_bfloat16 sB[2][128 * SROW];

    const int tid = threadIdx.x;
    const int warp = tid >> 5, lane = tid & 31;
    const int wm = warp & 1, wn = warp >> 1;   // 2 x 4 warp grid

    const __nv_bfloat16* Ag = (EPI == 0) ? g_Acat : g_Xcat;
    const __nv_bfloat16* Bg = (EPI == 0) ? g_Bq : g_Bp;

    // loader mapping: row = tid>>1, two 16B chunks at col (tid&1)*16 + {0,8}
    const int lrow = tid >> 1;
    const int lcol = (tid & 1) * 16;
    const __nv_bfloat16* Agp = Ag + (size_t)(blockIdx.y * 128 + lrow) * KC + lcol;
    const __nv_bfloat16* Bgp = Bg + (size_t)(blockIdx.x * 128 + lrow) * KC + lcol;

    const uint32_t sA0 = smem_u32(&sA[0][0]);
    const uint32_t sB0 = smem_u32(&sB[0][0]);
    const uint32_t bufsz = 128 * SROW * 2;     // bytes per buffer
    const uint32_t st_off = ((uint32_t)lrow * SROW + lcol) * 2;

    float acc[4][4][4];
#pragma unroll
    for (int i = 0; i < 4; i++)
#pragma unroll
        for (int j = 0; j < 4; j++)
#pragma unroll
            for (int k = 0; k < 4; k++) acc[i][j][k] = 0.f;

    // ldmatrix source addresses (per-thread, fixed except buffer/k-step offset)
    const int l15 = lane & 15;
    const uint32_t a_off = ((uint32_t)(wm * 64 + l15) * SROW + (lane >> 4) * 8) * 2;
    const uint32_t b_off = ((uint32_t)(wn * 32 + (l15 & 7)) * SROW + ((l15 >> 3) & 1) * 8) * 2;

    // preload iter 0
    {
        CP16(sA0 + st_off, Agp);
        CP16(sA0 + st_off + 16, Agp + 8);
        CP16(sB0 + st_off, Bgp);
        CP16(sB0 + st_off + 16, Bgp + 8);
        CP_COMMIT();
    }

    const int NIT = KC / 32;   // 72
    for (int it = 0; it < NIT; ++it) {
        const uint32_t abase = sA0 + (it & 1) * bufsz;
        const uint32_t bbase = sB0 + (it & 1) * bufsz;
        if (it + 1 < NIT) {
            const uint32_t na = sA0 + ((it + 1) & 1) * bufsz;
            const uint32_t nb = sB0 + ((it + 1) & 1) * bufsz;
            const int k0 = (it + 1) * 32;
            CP16(na + st_off, Agp + k0);
            CP16(na + st_off + 16, Agp + k0 + 8);
            CP16(nb + st_off, Bgp + k0);
            CP16(nb + st_off + 16, Bgp + k0 + 8);
            CP_COMMIT();
            CP_WAIT1();
        } else {
            CP_WAIT0();
        }
        __syncthreads();

#pragma unroll
        for (int ks = 0; ks < 2; ks++) {
            uint32_t a[4][4], b[4][2];
#pragma unroll
            for (int ma = 0; ma < 4; ma++)
                ldsm_x4(a[ma][0], a[ma][1], a[ma][2], a[ma][3],
                        abase + a_off + (ma * 16 * SROW + ks * 16) * 2);
#pragma unroll
            for (int na = 0; na < 4; na++)
                ldsm_x2(b[na][0], b[na][1],
                        bbase + b_off + (na * 8 * SROW + ks * 16) * 2);
#pragma unroll
            for (int ma = 0; ma < 4; ma++)
#pragma unroll
                for (int na = 0; na < 4; na++)
                    mma16816(acc[ma][na], a[ma], b[na]);
        }
        __syncthreads();
    }

    // ---------------- epilogue ----------------
#pragma unroll
    for (int ma = 0; ma < 4; ma++) {
        const int r0 = blockIdx.y * 128 + wm * 64 + ma * 16 + (lane >> 2);
#pragma unroll
        for (int na = 0; na < 4; na++) {
            const int c = blockIdx.x * 128 + wn * 32 + na * 8 + (lane & 3) * 2;
            if (EPI == 0) {
                const int which = c / 768;
                const int rem = c - which * 768;
                const int h = rem >> 6;
                const int dd = rem & 63;
                const float sc = (which < 2) ? QK_SCALE : 1.0f;
#pragma unroll
                for (int half = 0; half < 2; half++) {
                    const int r = r0 + half * 8;
                    const int b = r >> 11;
                    const int n = r & 2047;
                    float2 v;
                    v.x = acc[ma][na][2 * half + 0] * sc;
                    v.y = acc[ma][na][2 * half + 1] * sc;
                    *(float2*)(g_qkv + (((size_t)which * BH + b * Hn + h) * Nseq + n) * Dh + dd) = v;
                }
            } else {
                const float bx_ = bias[c], by_ = bias[c + 1];
#pragma unroll
                for (int half = 0; half < 2; half++) {
                    const int r = r0 + half * 8;
                    float2 v;
                    v.x = acc[ma][na][2 * half + 0] + bx_;
                    v.y = acc[ma][na][2 * half + 1] + by_;
                    *(float2*)(out + (size_t)r * Cdim + c) = v;
                }
            }
        }
    }
}

// ============================================================================
// Landmark pooling: mean over contiguous chunks of 64
// ============================================================================
__global__ void pool_kernel()
{
    int idx = blockIdx.x * 256 + threadIdx.x;
    int dd = idx & 63;
    int i = (idx >> 6) & 31;
    int rest = idx >> 11;            // which*96 + bh  (which in {0,1})
    const float* src = g_qkv + (size_t)rest * Nseq * Dh + (size_t)(i * 64) * Dh + dd;
    float s = 0.f;
#pragma unroll 8
    for (int t = 0; t < 64; t++) s += src[(size_t)t * Dh];
    g_lm[idx] = s * (1.0f / 64.0f);
}

// ============================================================================
// kernel_2 = softmax(Q_l K_l^T) + Newton-Schulz pseudo-inverse (6 iters)
// ============================================================================
__global__ __launch_bounds__(1024)
void newton_kernel()
{
    int bh = blockIdx.x;
    int j = threadIdx.x, i = threadIdx.y;
    __shared__ float Ql[32][65], Kl[32][65];
    __shared__ float Km[32][33], Vm[32][33], KV[32][33], Tm[32][33];
    __shared__ float red[1];

    int t = i * 32 + j;
    for (int e = t; e < Mlm * Dh; e += 1024) {
        Ql[e >> 6][e & 63] = g_lm[(size_t)bh * (Mlm * Dh) + e];
        Kl[e >> 6][e & 63] = g_lm[(size_t)(BH + bh) * (Mlm * Dh) + e];
    }
    __syncthreads();

    float s = 0.f;
#pragma unroll
    for (int dd = 0; dd < 64; dd++) s += Ql[i][dd] * Kl[j][dd];
    float mx = s;
    for (int o = 16; o; o >>= 1) mx = fmaxf(mx, __shfl_xor_sync(~0u, mx, o));
    float p = expf(s - mx);
    float sm = p;
    for (int o = 16; o; o >>= 1) sm += __shfl_xor_sync(~0u, sm, o);
    p /= sm;
    Km[i][j] = p;
    __syncthreads();

    if (i == 0) {
        float cs = 0.f;
        for (int r = 0; r < 32; r++) cs += Km[r][j];
        float m2 = cs;
        for (int o = 16; o; o >>= 1) m2 = fmaxf(m2, __shfl_xor_sync(~0u, m2, o));
        if (j == 0) red[0] = m2;
    }
    __syncthreads();
    float denom = red[0];
    Vm[i][j] = Km[j][i] / denom;
    __syncthreads();

    for (int it = 0; it < 6; it++) {
        float kv = 0.f;
#pragma unroll
        for (int k = 0; k < 32; k++) kv += Km[i][k] * Vm[k][j];
        KV[i][j] = kv;
        __syncthreads();
        Tm[i][j] = (i == j ? 7.0f : 0.0f) - kv;
        __syncthreads();
        float u = 0.f;
#pragma unroll
        for (int k = 0; k < 32; k++) u += KV[i][k] * Tm[k][j];
        __syncthreads();
        Tm[i][j] = (i == j ? 15.0f : 0.0f) - u;
        __syncthreads();
        u = 0.f;
#pragma unroll
        for (int k = 0; k < 32; k++) u += KV[i][k] * Tm[k][j];
        __syncthreads();
        Tm[i][j] = (i == j ? 13.0f : 0.0f) - u;
        __syncthreads();
        u = 0.f;
#pragma unroll
        for (int k = 0; k < 32; k++) u += Vm[i][k] * Tm[k][j];
        u *= 0.25f;
        __syncthreads();
        Vm[i][j] = u;
        __syncthreads();
    }
    g_inv[((size_t)bh * 32 + i) * 32 + j] = Vm[i][j];
}

// ============================================================================
// flash_k3_part: partial softmax(Q_l K^T) @ V over a 256-token chunk
// grid (96, 8), 512 threads: 16 warps x 2 landmark rows
// ============================================================================
__global__ __launch_bounds__(512)
void flash_k3_part()
{
    int bh = blockIdx.x;
    int chunk = blockIdx.y;
    int tid = threadIdx.x;
    int w = tid >> 5, l = tid & 31;
    __shared__ float Ql[32][65];
    __shared__ float Ks[32][65], Vs[32][65];
    __shared__ float Ps[32][33];

    const float* Kg = g_qkv + ((size_t)1 * BH + bh) * Nseq * Dh;
    const float* Vg = g_qkv + ((size_t)2 * BH + bh) * Nseq * Dh;

    for (int e = tid; e < Mlm * Dh; e += 512)
        Ql[e >> 6][e & 63] = g_lm[(size_t)bh * (Mlm * Dh) + e];

    const int r0 = w * 2, r1 = r0 + 1;
    float m0 = -1e30f, l0 = 0.f, o00 = 0.f, o01 = 0.f;
    float m1 = -1e30f, l1 = 0.f, o10 = 0.f, o11 = 0.f;

    const int tbeg = chunk * 256;
    for (int t0 = tbeg; t0 < tbeg + 256; t0 += 32) {
        __syncthreads();
        for (int e = tid; e < 32 * Dh; e += 512) {
            int rr = e >> 6, c = e & 63;
            Ks[rr][c] = Kg[(size_t)(t0 + rr) * Dh + c];
            Vs[rr][c] = Vg[(size_t)(t0 + rr) * Dh + c];
        }
        __syncthreads();
        {
            float s = 0.f;
#pragma unroll
            for (int dd = 0; dd < 64; dd++) s += Ql[r0][dd] * Ks[l][dd];
            float tm = s;
            for (int o = 16; o; o >>= 1) tm = fmaxf(tm, __shfl_xor_sync(~0u, tm, o));
            float nm = fmaxf(m0, tm);
            float alpha = expf(m0 - nm);
            float p = expf(s - nm);
            float ps = p;
            for (int o = 16; o; o >>= 1) ps += __shfl_xor_sync(~0u, ps, o);
            l0 = l0 * alpha + ps;
            o00 *= alpha; o01 *= alpha;
            Ps[r0][l] = p;
            __syncwarp();
#pragma unroll
            for (int k = 0; k < 32; k++) {
                float pk = Ps[r0][k];
                o00 += pk * Vs[k][2 * l];
                o01 += pk * Vs[k][2 * l + 1];
            }
            m0 = nm;
        }
        {
            float s = 0.f;
#pragma unroll
            for (int dd = 0; dd < 64; dd++) s += Ql[r1][dd] * Ks[l][dd];
            float tm = s;
            for (int o = 16; o; o >>= 1) tm = fmaxf(tm, __shfl_xor_sync(~0u, tm, o));
            float nm = fmaxf(m1, tm);
            float alpha = expf(m1 - nm);
            float p = expf(s - nm);
            float ps = p;
            for (int o = 16; o; o >>= 1) ps += __shfl_xor_sync(~0u, ps, o);
            l1 = l1 * alpha + ps;
            o10 *= alpha; o11 *= alpha;
            Ps[r1][l] = p;
            __syncwarp();
#pragma unroll
            for (int k = 0; k < 32; k++) {
                float pk = Ps[r1][k];
                o10 += pk * Vs[k][2 * l];
                o11 += pk * Vs[k][2 * l + 1];
            }
            m1 = nm;
        }
    }
    float* P0 = g_Fpart + (((size_t)bh * 8 + chunk) * Mlm + r0) * 66;
    float* P1 = g_Fpart + (((size_t)bh * 8 + chunk) * Mlm + r1) * 66;
    P0[2 * l] = o00; P0[2 * l + 1] = o01;
    P1[2 * l] = o10; P1[2 * l + 1] = o11;
    if (l == 0) { P0[64] = m0; P0[65] = l0; P1[64] = m1; P1[65] = l1; }
}

// combine 8 partials -> g_F  (grid 96, block (64,8))
__global__ __launch_bounds__(512)
void flash_combine()
{
    int bh = blockIdx.x;
    int d = threadIdx.x;
    for (int r = threadIdx.y; r < Mlm; r += 8) {
        const float* base = g_Fpart + (((size_t)bh * 8) * Mlm + r) * 66;
        float mstar = -1e30f;
#pragma unroll
        for (int c = 0; c < 8; c++) mstar = fmaxf(mstar, base[(size_t)c * Mlm * 66 + 64]);
        float L = 0.f, acc = 0.f;
#pragma unroll
        for (int c = 0; c < 8; c++) {
            const float* pc = base + (size_t)c * Mlm * 66;
            float e = expf(pc[64] - mstar);
            L += pc[65] * e;
            acc += pc[d] * e;
        }
        g_F[((size_t)bh * Mlm + r) * Dh + d] = acc / L;
    }
}

// ============================================================================
// X = softmax(Q K_l^T) @ (inv @ F)  -> writes bf16 split-cat rows of g_Xcat
// ============================================================================
__global__ __launch_bounds__(128)
void nys_out()
{
    int bh = blockIdx.y;
    int b = bh / Hn, h = bh - b * Hn;
    int chunk = blockIdx.x;
    int tid = threadIdx.x;

    __shared__ float Kl[32][65];
    __shared__ float Fs[32][65];
    __shared__ float Gs[32][65];
    __shared__ float invs[32][33];

    for (int e = tid; e < Mlm * Dh; e += 128) {
        Kl[e >> 6][e & 63] = g_lm[(size_t)(BH + bh) * (Mlm * Dh) + e];
        Fs[e >> 6][e & 63] = g_F[(size_t)bh * (Mlm * Dh) + e];
    }
    for (int e = tid; e < Mlm * Mlm; e += 128)
        invs[e >> 5][e & 31] = g_inv[(size_t)bh * (Mlm * Mlm) + e];
    __syncthreads();

    for (int e = tid; e < Mlm * Dh; e += 128) {
        int r = e >> 6, c = e & 63;
        float s = 0.f;
#pragma unroll
        for (int k = 0; k < 32; k++) s += invs[r][k] * Fs[k][c];
        Gs[r][c] = s;
    }
    __syncthreads();

    int n = chunk * 128 + tid;
    const float* Qg = g_qkv + ((size_t)bh * Nseq + n) * Dh;
    float q[64];
#pragma unroll
    for (int e = 0; e < 16; e++)
        *(float4*)&q[4 * e] = *(const float4*)&Qg[4 * e];

    float logits[32];
#pragma unroll
    for (int j = 0; j < 32; j++) {
        float s = 0.f;
#pragma unroll
        for (int dd = 0; dd < 64; dd++) s += q[dd] * Kl[j][dd];
        logits[j] = s;
    }
    float mx = -1e30f;
#pragma unroll
    for (int j = 0; j < 32; j++) mx = fmaxf(mx, logits[j]);
    float sum = 0.f;
#pragma unroll
    for (int j = 0; j < 32; j++) { logits[j] = expf(logits[j] - mx); sum += logits[j]; }
    float is = 1.f / sum;
#pragma unroll
    for (int j = 0; j < 32; j++) logits[j] *= is;

    // output row in X_cat: r = b*2048 + n, cols h*64 + dd (split-cat: [Xh|Xh|Xl])
    __nv_bfloat16* row = g_Xcat + ((size_t)b * Nseq + n) * KC + h * Dh;
#pragma unroll
    for (int d4 = 0; d4 < 16; d4++) {
        float o[4] = {0.f, 0.f, 0.f, 0.f};
#pragma unroll
        for (int j = 0; j < 32; j++) {
            float pj = logits[j];
            o[0] += pj * Gs[j][4 * d4 + 0];
            o[1] += pj * Gs[j][4 * d4 + 1];
            o[2] += pj * Gs[j][4 * d4 + 2];
            o[3] += pj * Gs[j][4 * d4 + 3];
        }
        __nv_bfloat16 hi[4], lo[4];
#pragma unroll
        for (int i = 0; i < 4; i++) {
            hi[i] = __float2bfloat16(o[i]);
            lo[i] = __float2bfloat16(o[i] - __bfloat162float(hi[i]));
        }
        __nv_bfloat162 h0 = {hi[0], hi[1]}, h1 = {hi[2], hi[3]};
        __nv_bfloat162 l0 = {lo[0], lo[1]}, l1 = {lo[2], lo[3]};
        int c = 4 * d4;
        *(__nv_bfloat162*)(row + c) = h0;        *(__nv_bfloat162*)(row + c + 2) = h1;
        *(__nv_bfloat162*)(row + 768 + c) = h0;  *(__nv_bfloat162*)(row + 768 + c + 2) = h1;
        *(__nv_bfloat162*)(row + 1536 + c) = l0; *(__nv_bfloat162*)(row + 1536 + c + 2) = l1;
    }
}

// ============================================================================
extern "C" void kernel_launch(void* const* d_in, const int* in_sizes, int n_in,
                              void* d_out, int out_size)
{
    const float* x      = (const float*)d_in[0];  // [8,2048,768]
    const float* w_qkv  = (const float*)d_in[1];  // [768,2304]
    const float* w_proj = (const float*)d_in[2];  // [768,768]
    const float* b_proj = (const float*)d_in[3];  // [768]
    float* out = (float*)d_out;                   // [8,2048,768]

    __nv_bfloat16 *gBq, *gBp;
    cudaGetSymbolAddress((void**)&gBq, g_Bq);
    cudaGetSymbolAddress((void**)&gBp, g_Bp);

    // 1. bf16 split conversions
    conv_a<<<16384 * 192 / 256, 256>>>(x);
    conv_w<<<dim3(KC / 32, Cdim / 32), dim3(32, 8)>>>(w_qkv, gBq, KC);
    conv_w<<<dim3(Cdim / 32, Cdim / 32), dim3(32, 8)>>>(w_proj, gBp, Cdim);
    // 2. qkv GEMM on HMMA (M=16384, N=2304, K'=2304) -> g_qkv (scaled)
    hmma_gemm<0><<<dim3(KC / 128, 16384 / 128), 256>>>(nullptr, nullptr);
    // 3. landmark pooling
    pool_kernel<<<2 * BH * Mlm * Dh / 256, 256>>>();
    // 4. kernel_2 + Newton-Schulz inverse
    newton_kernel<<<BH, dim3(32, 32)>>>();
    // 5. F = softmax(Q_l K^T) @ V  (split over 8 chunks + combine)
    flash_k3_part<<<dim3(BH, 8), 512>>>();
    flash_combine<<<BH, dim3(64, 8)>>>();
    // 6. X = softmax(Q K_l^T) @ (inv @ F) -> g_Xcat (bf16 split)
    nys_out<<<dim3(Nseq / 128, BH), 128>>>();
    // 7. proj GEMM on HMMA (M=16384, N=768, K'=2304) + bias -> out
    hmma_gemm<1><<<dim3(Cdim / 128, 16384 / 128), 256>>>(b_proj, out);
}

// round 8
// speedup vs baseline: 1.7605x; 1.0530x over previous
#include <cuda_runtime.h>
#include <cuda_bf16.h>
#include <math.h>
#include <stdint.h>

// Problem constants
#define Bsz 8
#define Nseq 2048
#define Cdim 768
#define Hn 12
#define Dh 64
#define Mlm 32
#define BH (Bsz*Hn)            // 96
#define KS 1536                // split storage width ([hi|lo])
#define QK_SCALE 0.35355339059327373f  // 64^-0.25

// ---------------- scratch (device globals; no runtime alloc allowed) -------
__device__ float g_qkv[(size_t)3 * BH * Nseq * Dh];         // [3][96][2048][64]
__device__ float g_lm[(size_t)2 * BH * Mlm * Dh];           // Q_l then K_l
__device__ float g_inv[(size_t)BH * Mlm * Mlm];             // pinv(kernel_2)
__device__ float g_F[(size_t)BH * Mlm * Dh];                // kernel_3 @ V
__device__ float g_Fpart[(size_t)BH * 8 * Mlm * 66];        // partial flash outputs
__device__ __nv_bfloat16 g_Acat[(size_t)16384 * KS];        // [Ah|Al] of x
__device__ __nv_bfloat16 g_Xcat[(size_t)16384 * KS];        // [Xh|Xl] of attention out
__device__ __nv_bfloat16 g_Bq[(size_t)2304 * KS];           // w_qkv^T split [N=2304][Bh|Bl]
__device__ __nv_bfloat16 g_Bp[(size_t)Cdim * KS];           // w_proj^T split [N=768][Bh|Bl]

// ============================================================================
// PTX helpers (baseline ISA only: cp.async / ldmatrix / mma.sync)
// ============================================================================
__device__ __forceinline__ uint32_t smem_u32(const void* p) {
    uint32_t a;
    asm("{ .reg .u64 t; cvta.to.shared.u64 t, %1; cvt.u32.u64 %0, t; }" : "=r"(a) : "l"(p));
    return a;
}
#define CP16(dst, src) \
    asm volatile("cp.async.cg.shared.global [%0], [%1], 16;" :: "r"(dst), "l"(src))
#define CP_COMMIT() asm volatile("cp.async.commit_group;" ::: "memory")
#define CP_WAIT2()  asm volatile("cp.async.wait_group 2;" ::: "memory")

__device__ __forceinline__ void ldsm_x4(uint32_t& r0, uint32_t& r1, uint32_t& r2, uint32_t& r3, uint32_t addr) {
    asm volatile("ldmatrix.sync.aligned.m8n8.x4.shared.b16 {%0,%1,%2,%3}, [%4];"
                 : "=r"(r0), "=r"(r1), "=r"(r2), "=r"(r3) : "r"(addr));
}
__device__ __forceinline__ void mma16816(float* d, const uint32_t* a, const uint32_t* b) {
    asm volatile("mma.sync.aligned.m16n8k16.row.col.f32.bf16.bf16.f32 "
                 "{%0,%1,%2,%3}, {%4,%5,%6,%7}, {%8,%9}, {%0,%1,%2,%3};"
                 : "+f"(d[0]), "+f"(d[1]), "+f"(d[2]), "+f"(d[3])
                 : "r"(a[0]), "r"(a[1]), "r"(a[2]), "r"(a[3]), "r"(b[0]), "r"(b[1]));
}

// K-index remap: 72 iterations of BK=32 realize 3 products
//   it [0,24): Ah*Bh   it [24,48): Ah*Bl   it [48,72): Al*Bh
__device__ __forceinline__ int kmapA(int it) {
    return (it < 48) ? (it % 24) * 32 : 768 + (it - 48) * 32;
}
__device__ __forceinline__ int kmapB(int it) {
    return (it < 24) ? it * 32 : ((it < 48) ? 768 + (it - 24) * 32 : (it - 48) * 32);
}

// ============================================================================
// conv_a: x [16384][768] f32 -> g_Acat [16384][1536] bf16  ([Ah|Al])
// ============================================================================
__global__ __launch_bounds__(256) void conv_a(const float* __restrict__ X)
{
    int idx = blockIdx.x * 256 + threadIdx.x;   // 16384*192 total
    int r = idx / 192, c = (idx - r * 192) * 4;
    float4 v = *(const float4*)(X + (size_t)r * Cdim + c);
    float f[4] = {v.x, v.y, v.z, v.w};
    __nv_bfloat16 hi[4], lo[4];
#pragma unroll
    for (int i = 0; i < 4; i++) {
        hi[i] = __float2bfloat16(f[i]);
        lo[i] = __float2bfloat16(f[i] - __bfloat162float(hi[i]));
    }
    __nv_bfloat16* row = g_Acat + (size_t)r * KS;
    __nv_bfloat162 h0 = {hi[0], hi[1]}, h1 = {hi[2], hi[3]};
    __nv_bfloat162 l0 = {lo[0], lo[1]}, l1 = {lo[2], lo[3]};
    *(__nv_bfloat162*)(row + c) = h0;        *(__nv_bfloat162*)(row + c + 2) = h1;
    *(__nv_bfloat162*)(row + 768 + c) = l0;  *(__nv_bfloat162*)(row + 768 + c + 2) = l1;
}

// ============================================================================
// conv_w: W [768][Nw] f32 -> Bt [Nw][1536] bf16 transposed split [Bh|Bl]
// ============================================================================
__global__ __launch_bounds__(256) void conv_w(const float* __restrict__ W,
                                              __nv_bfloat16* __restrict__ Bt, int Nw)
{
    __shared__ float tile[32][33];
    int n0 = blockIdx.x * 32, k0 = blockIdx.y * 32;
    for (int i = threadIdx.y; i < 32; i += 8)
        tile[i][threadIdx.x] = W[(size_t)(k0 + i) * Nw + n0 + threadIdx.x];
    __syncthreads();
    for (int i = threadIdx.y; i < 32; i += 8) {
        int n = n0 + i, k = k0 + threadIdx.x;
        float v = tile[threadIdx.x][i];
        __nv_bfloat16 hi = __float2bfloat16(v);
        __nv_bfloat16 lo = __float2bfloat16(v - __bfloat162float(hi));
        __nv_bfloat16* row = Bt + (size_t)n * KS;
        row[k] = hi;
        row[768 + k] = lo;
    }
}

// ============================================================================
// HMMA bf16 GEMM: D[128x128] = sum of 3 split products (72 BK=32 steps)
// 256 threads = 8 warps (2x4), warp tile 64x32.
// 4-stage cp.async pipeline, one __syncthreads per iteration.
// EPI 0: scatter into g_qkv with QK scale.  EPI 1: +bias -> out.
// ============================================================================
#define SROW 40                 // smem row stride in bf16 (80B)
#define ASZ  (128 * SROW * 2)   // bytes per A (or B) stage = 10240
#define STAGE_BYTES (2 * ASZ)   // 20480
#define GEMM_SMEM (4 * STAGE_BYTES)  // 81920

template<int EPI>
__global__ __launch_bounds__(256)
void hmma_gemm(const float* __restrict__ bias, float* __restrict__ out)
{
    extern __shared__ __align__(16) char dsm[];
    const uint32_t smem0 = smem_u32(dsm);

    const int tid = threadIdx.x;
    const int warp = tid >> 5, lane = tid & 31;
    const int wm = warp & 1, wn = warp >> 1;   // 2 x 4 warp grid

    const __nv_bfloat16* Ag = (EPI == 0) ? g_Acat : g_Xcat;
    const __nv_bfloat16* Bg = (EPI == 0) ? g_Bq : g_Bp;

    // loader mapping: row = tid>>1, 32B at col (tid&1)*16
    const int lrow = tid >> 1;
    const int lcol = (tid & 1) * 16;
    const __nv_bfloat16* Agp = Ag + (size_t)(blockIdx.y * 128 + lrow) * KS + lcol;
    const __nv_bfloat16* Bgp = Bg + (size_t)(blockIdx.x * 128 + lrow) * KS + lcol;
    const uint32_t st_off = ((uint32_t)lrow * SROW + lcol) * 2;

    float acc[4][4][4];
#pragma unroll
    for (int i = 0; i < 4; i++)
#pragma unroll
        for (int j = 0; j < 4; j++)
#pragma unroll
            for (int k = 0; k < 4; k++) acc[i][j][k] = 0.f;

    // ldmatrix per-thread offsets
    const int l15 = lane & 15;
    const uint32_t a_off = ((uint32_t)(wm * 64 + l15) * SROW + (lane >> 4) * 8) * 2;
    // B x4: lanes 0-7 m0(n0-7,k0-7), 8-15 m1(n0-7,k8-15), 16-23 m2(n8-15,k0-7), 24-31 m3
    const uint32_t b_off = ((uint32_t)(wn * 32 + ((lane >> 4) & 1) * 8 + (lane & 7)) * SROW
                           + ((lane >> 3) & 1) * 8) * 2;

    const int NIT = 72;
    // prologue: stages 0..2
#pragma unroll
    for (int s = 0; s < 3; s++) {
        const uint32_t sa = smem0 + s * STAGE_BYTES;
        const uint32_t sb = sa + ASZ;
        const int kA = kmapA(s), kB = kmapB(s);
        CP16(sa + st_off, Agp + kA);
        CP16(sa + st_off + 16, Agp + kA + 8);
        CP16(sb + st_off, Bgp + kB);
        CP16(sb + st_off + 16, Bgp + kB + 8);
        CP_COMMIT();
    }

    for (int it = 0; it < NIT; ++it) {
        CP_WAIT2();           // stage `it` resident
        __syncthreads();      // all warps done with buffer (it-1)%4

        if (it + 3 < NIT) {   // refill buffer (it+3)%4
            const uint32_t sa = smem0 + ((it + 3) & 3) * STAGE_BYTES;
            const uint32_t sb = sa + ASZ;
            const int kA = kmapA(it + 3), kB = kmapB(it + 3);
            CP16(sa + st_off, Agp + kA);
            CP16(sa + st_off + 16, Agp + kA + 8);
            CP16(sb + st_off, Bgp + kB);
            CP16(sb + st_off + 16, Bgp + kB + 8);
        }
        CP_COMMIT();          // always commit (empty groups keep count exact)

        const uint32_t abase = smem0 + (it & 3) * STAGE_BYTES;
        const uint32_t bbase = abase + ASZ;
#pragma unroll
        for (int ks = 0; ks < 2; ks++) {
            uint32_t a[4][4], b[4][2];
#pragma unroll
            for (int ma = 0; ma < 4; ma++)
                ldsm_x4(a[ma][0], a[ma][1], a[ma][2], a[ma][3],
                        abase + a_off + (ma * 16 * SROW + ks * 16) * 2);
#pragma unroll
            for (int nb = 0; nb < 2; nb++)
                ldsm_x4(b[2 * nb][0], b[2 * nb][1], b[2 * nb + 1][0], b[2 * nb + 1][1],
                        bbase + b_off + (nb * 16 * SROW + ks * 16) * 2);
#pragma unroll
            for (int ma = 0; ma < 4; ma++)
#pragma unroll
                for (int na = 0; na < 4; na++)
                    mma16816(acc[ma][na], a[ma], b[na]);
        }
    }

    // ---------------- epilogue ----------------
#pragma unroll
    for (int ma = 0; ma < 4; ma++) {
        const int r0 = blockIdx.y * 128 + wm * 64 + ma * 16 + (lane >> 2);
#pragma unroll
        for (int na = 0; na < 4; na++) {
            const int c = blockIdx.x * 128 + wn * 32 + na * 8 + (lane & 3) * 2;
            if (EPI == 0) {
                const int which = c / 768;
                const int rem = c - which * 768;
                const int h = rem >> 6;
                const int dd = rem & 63;
                const float sc = (which < 2) ? QK_SCALE : 1.0f;
#pragma unroll
                for (int half = 0; half < 2; half++) {
                    const int r = r0 + half * 8;
                    const int b = r >> 11;
                    const int n = r & 2047;
                    float2 v;
                    v.x = acc[ma][na][2 * half + 0] * sc;
                    v.y = acc[ma][na][2 * half + 1] * sc;
                    *(float2*)(g_qkv + (((size_t)which * BH + b * Hn + h) * Nseq + n) * Dh + dd) = v;
                }
            } else {
                const float bx_ = bias[c], by_ = bias[c + 1];
#pragma unroll
                for (int half = 0; half < 2; half++) {
                    const int r = r0 + half * 8;
                    float2 v;
                    v.x = acc[ma][na][2 * half + 0] + bx_;
                    v.y = acc[ma][na][2 * half + 1] + by_;
                    *(float2*)(out + (size_t)r * Cdim + c) = v;
                }
            }
        }
    }
}

// ============================================================================
// Landmark pooling: mean over contiguous chunks of 64
// ============================================================================
__global__ void pool_kernel()
{
    int idx = blockIdx.x * 256 + threadIdx.x;
    int dd = idx & 63;
    int i = (idx >> 6) & 31;
    int rest = idx >> 11;            // which*96 + bh  (which in {0,1})
    const float* src = g_qkv + (size_t)rest * Nseq * Dh + (size_t)(i * 64) * Dh + dd;
    float s = 0.f;
#pragma unroll 8
    for (int t = 0; t < 64; t++) s += src[(size_t)t * Dh];
    g_lm[idx] = s * (1.0f / 64.0f);
}

// ============================================================================
// kernel_2 = softmax(Q_l K_l^T) + Newton-Schulz pseudo-inverse (6 iters)
// ============================================================================
__global__ __launch_bounds__(1024)
void newton_kernel()
{
    int bh = blockIdx.x;
    int j = threadIdx.x, i = threadIdx.y;
    __shared__ float Ql[32][65], Kl[32][65];
    __shared__ float Km[32][33], Vm[32][33], KV[32][33], Tm[32][33];
    __shared__ float red[1];

    int t = i * 32 + j;
    for (int e = t; e < Mlm * Dh; e += 1024) {
        Ql[e >> 6][e & 63] = g_lm[(size_t)bh * (Mlm * Dh) + e];
        Kl[e >> 6][e & 63] = g_lm[(size_t)(BH + bh) * (Mlm * Dh) + e];
    }
    __syncthreads();

    float s = 0.f;
#pragma unroll
    for (int dd = 0; dd < 64; dd++) s += Ql[i][dd] * Kl[j][dd];
    float mx = s;
    for (int o = 16; o; o >>= 1) mx = fmaxf(mx, __shfl_xor_sync(~0u, mx, o));
    float p = expf(s - mx);
    float sm = p;
    for (int o = 16; o; o >>= 1) sm += __shfl_xor_sync(~0u, sm, o);
    p /= sm;
    Km[i][j] = p;
    __syncthreads();

    if (i == 0) {
        float cs = 0.f;
        for (int r = 0; r < 32; r++) cs += Km[r][j];
        float m2 = cs;
        for (int o = 16; o; o >>= 1) m2 = fmaxf(m2, __shfl_xor_sync(~0u, m2, o));
        if (j == 0) red[0] = m2;
    }
    __syncthreads();
    float denom = red[0];
    Vm[i][j] = Km[j][i] / denom;
    __syncthreads();

    for (int it = 0; it < 6; it++) {
        float kv = 0.f;
#pragma unroll
        for (int k = 0; k < 32; k++) kv += Km[i][k] * Vm[k][j];
        KV[i][j] = kv;
        __syncthreads();
        Tm[i][j] = (i == j ? 7.0f : 0.0f) - kv;
        __syncthreads();
        float u = 0.f;
#pragma unroll
        for (int k = 0; k < 32; k++) u += KV[i][k] * Tm[k][j];
        __syncthreads();
        Tm[i][j] = (i == j ? 15.0f : 0.0f) - u;
        __syncthreads();
        u = 0.f;
#pragma unroll
        for (int k = 0; k < 32; k++) u += KV[i][k] * Tm[k][j];
        __syncthreads();
        Tm[i][j] = (i == j ? 13.0f : 0.0f) - u;
        __syncthreads();
        u = 0.f;
#pragma unroll
        for (int k = 0; k < 32; k++) u += Vm[i][k] * Tm[k][j];
        u *= 0.25f;
        __syncthreads();
        Vm[i][j] = u;
        __syncthreads();
    }
    g_inv[((size_t)bh * 32 + i) * 32 + j] = Vm[i][j];
}

// ============================================================================
// flash_k3_part: partial softmax(Q_l K^T) @ V over a 256-token chunk
// grid (96, 8), 512 threads: 16 warps x 2 landmark rows
// ============================================================================
__global__ __launch_bounds__(512)
void flash_k3_part()
{
    int bh = blockIdx.x;
    int chunk = blockIdx.y;
    int tid = threadIdx.x;
    int w = tid >> 5, l = tid & 31;
    __shared__ float Ql[32][65];
    __shared__ float Ks[32][65], Vs[32][65];
    __shared__ float Ps[32][33];

    const float* Kg = g_qkv + ((size_t)1 * BH + bh) * Nseq * Dh;
    const float* Vg = g_qkv + ((size_t)2 * BH + bh) * Nseq * Dh;

    for (int e = tid; e < Mlm * Dh; e += 512)
        Ql[e >> 6][e & 63] = g_lm[(size_t)bh * (Mlm * Dh) + e];

    const int r0 = w * 2, r1 = r0 + 1;
    float m0 = -1e30f, l0 = 0.f, o00 = 0.f, o01 = 0.f;
    float m1 = -1e30f, l1 = 0.f, o10 = 0.f, o11 = 0.f;

    const int tbeg = chunk * 256;
    for (int t0 = tbeg; t0 < tbeg + 256; t0 += 32) {
        __syncthreads();
        for (int e = tid; e < 32 * Dh; e += 512) {
            int rr = e >> 6, c = e & 63;
            Ks[rr][c] = Kg[(size_t)(t0 + rr) * Dh + c];
            Vs[rr][c] = Vg[(size_t)(t0 + rr) * Dh + c];
        }
        __syncthreads();
        {
            float s = 0.f;
#pragma unroll
            for (int dd = 0; dd < 64; dd++) s += Ql[r0][dd] * Ks[l][dd];
            float tm = s;
            for (int o = 16; o; o >>= 1) tm = fmaxf(tm, __shfl_xor_sync(~0u, tm, o));
            float nm = fmaxf(m0, tm);
            float alpha = expf(m0 - nm);
            float p = expf(s - nm);
            float ps = p;
            for (int o = 16; o; o >>= 1) ps += __shfl_xor_sync(~0u, ps, o);
            l0 = l0 * alpha + ps;
            o00 *= alpha; o01 *= alpha;
            Ps[r0][l] = p;
            __syncwarp();
#pragma unroll
            for (int k = 0; k < 32; k++) {
                float pk = Ps[r0][k];
                o00 += pk * Vs[k][2 * l];
                o01 += pk * Vs[k][2 * l + 1];
            }
            m0 = nm;
        }
        {
            float s = 0.f;
#pragma unroll
            for (int dd = 0; dd < 64; dd++) s += Ql[r1][dd] * Ks[l][dd];
            float tm = s;
            for (int o = 16; o; o >>= 1) tm = fmaxf(tm, __shfl_xor_sync(~0u, tm, o));
            float nm = fmaxf(m1, tm);
            float alpha = expf(m1 - nm);
            float p = expf(s - nm);
            float ps = p;
            for (int o = 16; o; o >>= 1) ps += __shfl_xor_sync(~0u, ps, o);
            l1 = l1 * alpha + ps;
            o10 *= alpha; o11 *= alpha;
            Ps[r1][l] = p;
            __syncwarp();
#pragma unroll
            for (int k = 0; k < 32; k++) {
                float pk = Ps[r1][k];
                o10 += pk * Vs[k][2 * l];
                o11 += pk * Vs[k][2 * l + 1];
            }
            m1 = nm;
        }
    }
    float* P0 = g_Fpart + (((size_t)bh * 8 + chunk) * Mlm + r0) * 66;
    float* P1 = g_Fpart + (((size_t)bh * 8 + chunk) * Mlm + r1) * 66;
    P0[2 * l] = o00; P0[2 * l + 1] = o01;
    P1[2 * l] = o10; P1[2 * l + 1] = o11;
    if (l == 0) { P0[64] = m0; P0[65] = l0; P1[64] = m1; P1[65] = l1; }
}

// combine 8 partials -> g_F  (grid 96, block (64,8))
__global__ __launch_bounds__(512)
void flash_combine()
{
    int bh = blockIdx.x;
    int d = threadIdx.x;
    for (int r = threadIdx.y; r < Mlm; r += 8) {
        const float* base = g_Fpart + (((size_t)bh * 8) * Mlm + r) * 66;
        float mstar = -1e30f;
#pragma unroll
        for (int c = 0; c < 8; c++) mstar = fmaxf(mstar, base[(size_t)c * Mlm * 66 + 64]);
        float L = 0.f, acc = 0.f;
#pragma unroll
        for (int c = 0; c < 8; c++) {
            const float* pc = base + (size_t)c * Mlm * 66;
            float e = expf(pc[64] - mstar);
            L += pc[65] * e;
            acc += pc[d] * e;
        }
        g_F[((size_t)bh * Mlm + r) * Dh + d] = acc / L;
    }
}

// ============================================================================
// X = softmax(Q K_l^T) @ (inv @ F)  -> writes bf16 split rows of g_Xcat
// ============================================================================
__global__ __launch_bounds__(128)
void nys_out()
{
    int bh = blockIdx.y;
    int b = bh / Hn, h = bh - b * Hn;
    int chunk = blockIdx.x;
    int tid = threadIdx.x;

    __shared__ float Kl[32][65];
    __shared__ float Fs[32][65];
    __shared__ float Gs[32][65];
    __shared__ float invs[32][33];

    for (int e = tid; e < Mlm * Dh; e += 128) {
        Kl[e >> 6][e & 63] = g_lm[(size_t)(BH + bh) * (Mlm * Dh) + e];
        Fs[e >> 6][e & 63] = g_F[(size_t)bh * (Mlm * Dh) + e];
    }
    for (int e = tid; e < Mlm * Mlm; e += 128)
        invs[e >> 5][e & 31] = g_inv[(size_t)bh * (Mlm * Mlm) + e];
    __syncthreads();

    for (int e = tid; e < Mlm * Dh; e += 128) {
        int r = e >> 6, c = e & 63;
        float s = 0.f;
#pragma unroll
        for (int k = 0; k < 32; k++) s += invs[r][k] * Fs[k][c];
        Gs[r][c] = s;
    }
    __syncthreads();

    int n = chunk * 128 + tid;
    const float* Qg = g_qkv + ((size_t)bh * Nseq + n) * Dh;
    float q[64];
#pragma unroll
    for (int e = 0; e < 16; e++)
        *(float4*)&q[4 * e] = *(const float4*)&Qg[4 * e];

    float logits[32];
#pragma unroll
    for (int j = 0; j < 32; j++) {
        float s = 0.f;
#pragma unroll
        for (int dd = 0; dd < 64; dd++) s += q[dd] * Kl[j][dd];
        logits[j] = s;
    }
    float mx = -1e30f;
#pragma unroll
    for (int j = 0; j < 32; j++) mx = fmaxf(mx, logits[j]);
    float sum = 0.f;
#pragma unroll
    for (int j = 0; j < 32; j++) { logits[j] = expf(logits[j] - mx); sum += logits[j]; }
    float is = 1.f / sum;
#pragma unroll
    for (int j = 0; j < 32; j++) logits[j] *= is;

    // output row in X_cat: r = b*2048 + n, cols h*64 + dd (split: [Xh|Xl])
    __nv_bfloat16* row = g_Xcat + ((size_t)b * Nseq + n) * KS + h * Dh;
#pragma unroll
    for (int d4 = 0; d4 < 16; d4++) {
        float o[4] = {0.f, 0.f, 0.f, 0.f};
#pragma unroll
        for (int j = 0; j < 32; j++) {
            float pj = logits[j];
            o[0] += pj * Gs[j][4 * d4 + 0];
            o[1] += pj * Gs[j][4 * d4 + 1];
            o[2] += pj * Gs[j][4 * d4 + 2];
            o[3] += pj * Gs[j][4 * d4 + 3];
        }
        __nv_bfloat16 hi[4], lo[4];
#pragma unroll
        for (int i = 0; i < 4; i++) {
            hi[i] = __float2bfloat16(o[i]);
            lo[i] = __float2bfloat16(o[i] - __bfloat162float(hi[i]));
        }
        __nv_bfloat162 h0 = {hi[0], hi[1]}, h1 = {hi[2], hi[3]};
        __nv_bfloat162 l0 = {lo[0], lo[1]}, l1 = {lo[2], lo[3]};
        int c = 4 * d4;
        *(__nv_bfloat162*)(row + c) = h0;        *(__nv_bfloat162*)(row + c + 2) = h1;
        *(__nv_bfloat162*)(row + 768 + c) = l0;  *(__nv_bfloat162*)(row + 768 + c + 2) = l1;
    }
}

// ============================================================================
extern "C" void kernel_launch(void* const* d_in, const int* in_sizes, int n_in,
                              void* d_out, int out_size)
{
    const float* x      = (const float*)d_in[0];  // [8,2048,768]
    const float* w_qkv  = (const float*)d_in[1];  // [768,2304]
    const float* w_proj = (const float*)d_in[2];  // [768,768]
    const float* b_proj = (const float*)d_in[3];  // [768]
    float* out = (float*)d_out;                   // [8,2048,768]

    __nv_bfloat16 *gBq, *gBp;
    cudaGetSymbolAddress((void**)&gBq, g_Bq);
    cudaGetSymbolAddress((void**)&gBp, g_Bp);

    // allow >48KB dynamic smem for the GEMMs (host-side attribute set; idempotent)
    static int attr_done = 0;
    if (!attr_done) {
        cudaFuncSetAttribute(hmma_gemm<0>, cudaFuncAttributeMaxDynamicSharedMemorySize, GEMM_SMEM);
        cudaFuncSetAttribute(hmma_gemm<1>, cudaFuncAttributeMaxDynamicSharedMemorySize, GEMM_SMEM);
        attr_done = 1;
    }

    // 1. bf16 split conversions
    conv_a<<<16384 * 192 / 256, 256>>>(x);
    conv_w<<<dim3(2304 / 32, Cdim / 32), dim3(32, 8)>>>(w_qkv, gBq, 2304);
    conv_w<<<dim3(Cdim / 32, Cdim / 32), dim3(32, 8)>>>(w_proj, gBp, Cdim);
    // 2. qkv GEMM on HMMA (M=16384, N=2304, K=768 x 3 products) -> g_qkv (scaled)
    hmma_gemm<0><<<dim3(2304 / 128, 16384 / 128), 256, GEMM_SMEM>>>(nullptr, nullptr);
    // 3. landmark pooling
    pool_kernel<<<2 * BH * Mlm * Dh / 256, 256>>>();
    // 4. kernel_2 + Newton-Schulz inverse
    newton_kernel<<<BH, dim3(32, 32)>>>();
    // 5. F = softmax(Q_l K^T) @ V  (split over 8 chunks + combine)
    flash_k3_part<<<dim3(BH, 8), 512>>>();
    flash_combine<<<BH, dim3(64, 8)>>>();
    // 6. X = softmax(Q K_l^T) @ (inv @ F) -> g_Xcat (bf16 split)
    nys_out<<<dim3(Nseq / 128, BH), 128>>>();
    // 7. proj GEMM on HMMA (M=16384, N=768, K=768 x 3 products) + bias -> out
    hmma_gemm<1><<<dim3(Cdim / 128, 16384 / 128), 256, GEMM_SMEM>>>(b_proj, out);
}